// round 6
// baseline (speedup 1.0000x reference)
#include <cuda_runtime.h>
#include <cstdint>

#define BB 32
#define CC 384
#define TT 512
#define MF 6656           // MAX_FRAMES = 512*13
#define SPAN_MAX 144      // token-window capacity for smem-staged gather

// Scratch token map: tok[b][p] = source token index, -1 = masked
__device__ int16_t g_tok[BB * MF];

// ---------------------------------------------------------------------------
// prep: repeat counts -> inclusive scan -> searchsorted fill of token map,
// pitch output, frame_lengths. One block per batch, 512 threads.
// ---------------------------------------------------------------------------
__global__ void prep_kernel(const float* __restrict__ duration,
                            const float* __restrict__ notepitch,
                            float* __restrict__ out) {
    const int b = blockIdx.x;
    const int t = threadIdx.x;  // 0..511
    __shared__ int   s[TT];     // inclusive cumsum
    __shared__ float sp[TT];    // pitch values (int-cast)

    // repeat count, bit-exact vs jax float32 reference
    const float d  = duration[b * TT + t];
    const float fr = 44100.0f * d;
    float rf;
    if (fr - 1024.0f > 0.0f)
        rf = fmaxf((fr - 1024.0f) * (1.0f / 256.0f), 1.0f);  // /256 exact
    else
        rf = (d == 0.0f) ? 0.0f : 1.0f;
    const int r = (int)rf;

    sp[t] = (float)(int)notepitch[b * TT + t];

    // inclusive block scan (Hillis-Steele)
    s[t] = r;
    __syncthreads();
    #pragma unroll
    for (int off = 1; off < TT; off <<= 1) {
        int v = (t >= off) ? s[t - off] : 0;
        __syncthreads();
        s[t] += v;
        __syncthreads();
    }
    const int flen = s[TT - 1];

    float*   pitch_out = out + (size_t)BB * CC * MF + (size_t)b * MF;
    int16_t* tokb      = g_tok + b * MF;

    // cooperative searchsorted(right): idx = #elements of cum <= p
    for (int p = t; p < MF; p += TT) {
        if (p < flen) {
            int idx = 0;
            #pragma unroll
            for (int step = 256; step > 0; step >>= 1) {
                int cand = idx + step;
                if (cand <= TT && s[cand - 1] <= p) idx = cand;
            }
            // p < flen = s[511] guarantees idx <= 511
            tokb[p]      = (int16_t)idx;
            pitch_out[p] = sp[idx];
        } else {
            tokb[p]      = -1;
            pitch_out[p] = 0.0f;
        }
    }
    if (t == 0) {
        out[(size_t)BB * CC * MF + (size_t)BB * MF + b] = (float)flen;
    }
}

// ---------------------------------------------------------------------------
// expand: out[b, c, p] = tok[p]>=0 ? x[b, c, tok[p]] : 0
// grid = (MF/512, CC/32, BB), block = 128 threads, 4 frames/thread.
// Paths: (a) fully-masked block -> pure zero streaming stores
//        (b) token span <= SPAN_MAX -> stage x window in smem, LDS gather
//        (c) fallback -> direct gmem gather (rare; correctness guard)
// ---------------------------------------------------------------------------
__global__ void expand_kernel(const float* __restrict__ x,
                              float* __restrict__ out) {
    const int b   = blockIdx.z;
    const int c0  = blockIdx.y * 32;
    const int tid = threadIdx.x;
    const int p0  = blockIdx.x * 512 + tid * 4;

    __shared__ float xs[32 * SPAN_MAX];
    __shared__ int red_mn[4], red_mx[4];

    const short4 tk4 = *reinterpret_cast<const short4*>(g_tok + b * MF + p0);
    int t0 = tk4.x, t1 = tk4.y, t2 = tk4.z, t3 = tk4.w;
    const bool m0 = t0 >= 0, m1 = t1 >= 0, m2 = t2 >= 0, m3 = t3 >= 0;

    // block min/max over valid tokens
    int mn = 0x7fffffff, mx = -1;
    if (m0) { mn = min(mn, t0); mx = max(mx, t0); }
    if (m1) { mn = min(mn, t1); mx = max(mx, t1); }
    if (m2) { mn = min(mn, t2); mx = max(mx, t2); }
    if (m3) { mn = min(mn, t3); mx = max(mx, t3); }
    #pragma unroll
    for (int o = 16; o > 0; o >>= 1) {
        mn = min(mn, __shfl_xor_sync(0xffffffffu, mn, o));
        mx = max(mx, __shfl_xor_sync(0xffffffffu, mx, o));
    }
    const int wid = tid >> 5;
    if ((tid & 31) == 0) { red_mn[wid] = mn; red_mx[wid] = mx; }
    __syncthreads();
    mn = min(min(red_mn[0], red_mn[1]), min(red_mn[2], red_mn[3]));
    mx = max(max(red_mx[0], red_mx[1]), max(red_mx[2], red_mx[3]));

    float* ob = out + ((size_t)b * CC + c0) * MF + p0;

    if (mx < 0) {
        // fully masked: pure zero streaming stores
        const float4 z = make_float4(0.f, 0.f, 0.f, 0.f);
        #pragma unroll 8
        for (int c = 0; c < 32; ++c)
            *reinterpret_cast<float4*>(ob + (size_t)c * MF) = z;
        return;
    }

    const int span = mx - mn + 1;
    const float* xb = x + ((size_t)b * CC + c0) * TT;

    if (span <= SPAN_MAX) {
        // stage x[c0..c0+31][mn..mx] in smem (coalesced streaming reads)
        for (int c = 0; c < 32; ++c) {
            const float* xr = xb + c * TT + mn;
            for (int i = tid; i < span; i += 128)
                xs[c * SPAN_MAX + i] = xr[i];
        }
        __syncthreads();

        const int i0 = t0 - mn, i1 = t1 - mn, i2 = t2 - mn, i3 = t3 - mn;
        #pragma unroll 4
        for (int c = 0; c < 32; ++c) {
            const float* xr = xs + c * SPAN_MAX;
            float4 v;
            v.x = m0 ? xr[i0] : 0.0f;
            v.y = m1 ? xr[i1] : 0.0f;
            v.z = m2 ? xr[i2] : 0.0f;
            v.w = m3 ? xr[i3] : 0.0f;
            *reinterpret_cast<float4*>(ob + (size_t)c * MF) = v;
        }
    } else {
        // fallback: direct gmem gather
        int a0 = t0 & (TT - 1), a1 = t1 & (TT - 1), a2 = t2 & (TT - 1), a3 = t3 & (TT - 1);
        #pragma unroll 4
        for (int c = 0; c < 32; ++c) {
            const float* xr = xb + c * TT;
            float4 v;
            v.x = m0 ? xr[a0] : 0.0f;
            v.y = m1 ? xr[a1] : 0.0f;
            v.z = m2 ? xr[a2] : 0.0f;
            v.w = m3 ? xr[a3] : 0.0f;
            *reinterpret_cast<float4*>(ob + (size_t)c * MF) = v;
        }
    }
}

extern "C" void kernel_launch(void* const* d_in, const int* in_sizes, int n_in,
                              void* d_out, int out_size) {
    const float* x         = (const float*)d_in[0];
    const float* notepitch = (const float*)d_in[1];
    const float* duration  = (const float*)d_in[2];
    // d_in[3] = x_lengths: unused by the reference computation
    float* out = (float*)d_out;

    prep_kernel<<<BB, TT>>>(duration, notepitch, out);
    expand_kernel<<<dim3(MF / 512, CC / 32, BB), 128>>>(x, out);
}

// round 7
// speedup vs baseline: 1.0592x; 1.0592x over previous
#include <cuda_runtime.h>
#include <cstdint>

#define BB 32
#define CC 384
#define TT 512
#define MF 6656  // MAX_FRAMES = 512*13

// Scratch token map: tok[b][p] = source token index, -1 = masked
__device__ int16_t g_tok[BB * MF];

// ---------------------------------------------------------------------------
// prep: repeat counts -> inclusive scan -> scatter token map, pitch output,
// frame_lengths. One block per batch, 512 threads.
// ---------------------------------------------------------------------------
__global__ void prep_kernel(const float* __restrict__ duration,
                            const float* __restrict__ notepitch,
                            float* __restrict__ out) {
    const int b = blockIdx.x;
    const int t = threadIdx.x;  // 0..511
    __shared__ int s[TT];

    // repeat count, bit-exact vs jax float32 reference
    const float d  = duration[b * TT + t];
    const float fr = 44100.0f * d;
    float rf;
    if (fr - 1024.0f > 0.0f)
        rf = fmaxf((fr - 1024.0f) * (1.0f / 256.0f), 1.0f);  // /256 exact
    else
        rf = (d == 0.0f) ? 0.0f : 1.0f;
    const int r = (int)rf;

    // inclusive block scan (Hillis-Steele)
    s[t] = r;
    __syncthreads();
    #pragma unroll
    for (int off = 1; off < TT; off <<= 1) {
        int v = (t >= off) ? s[t - off] : 0;
        __syncthreads();
        s[t] += v;
        __syncthreads();
    }
    const int end   = s[t];
    const int start = (t == 0) ? 0 : s[t - 1];
    const int flen  = s[TT - 1];

    float*   pitch_out = out + (size_t)BB * CC * MF + (size_t)b * MF;
    int16_t* tokb      = g_tok + b * MF;

    // pitch value: int32 cast then back to float
    const float pv = (float)(int)notepitch[b * TT + t];

    // scatter: token t covers frames [start, end)
    for (int p = start; p < end; ++p) {
        tokb[p]      = (int16_t)t;
        pitch_out[p] = pv;
    }
    // masked tail: frames [flen, MF)
    for (int p = flen + t; p < MF; p += TT) {
        tokb[p]      = -1;
        pitch_out[p] = 0.0f;
    }
    if (t == 0) {
        out[(size_t)BB * CC * MF + (size_t)BB * MF + b] = (float)flen;
    }
}

// ---------------------------------------------------------------------------
// expand: out[b, c, p] = tok[p]>=0 ? x[b, c, tok[p]] : 0
// grid = (MF/512, CC/32, BB), block = 128 threads, 4 frames/thread.
// 4-channel batched gathers (16 LDGs in flight) then 4 STG.128s.
// Warp-level zero fast path for fully-masked warps (no smem, no sync).
// ---------------------------------------------------------------------------
__global__ void __launch_bounds__(128) expand_kernel(
        const float* __restrict__ x,
        float* __restrict__ out) {
    const int b   = blockIdx.z;
    const int c0  = blockIdx.y * 32;
    const int tid = threadIdx.x;
    const int p0  = blockIdx.x * 512 + tid * 4;

    const short4 tk4 = *reinterpret_cast<const short4*>(g_tok + b * MF + p0);
    int t0 = tk4.x, t1 = tk4.y, t2 = tk4.z, t3 = tk4.w;
    const bool m0 = t0 >= 0, m1 = t1 >= 0, m2 = t2 >= 0, m3 = t3 >= 0;

    float* ob = out + ((size_t)b * CC + c0) * MF + p0;

    const unsigned ball = __ballot_sync(0xffffffffu, m0 | m1 | m2 | m3);
    if (ball == 0u) {
        // fully-masked warp: pure streaming zero stores
        const float4 z = make_float4(0.f, 0.f, 0.f, 0.f);
        #pragma unroll 8
        for (int c = 0; c < 32; ++c)
            __stcs(reinterpret_cast<float4*>(ob + (size_t)c * MF), z);
        return;
    }

    // clamp masked tokens to a valid address (value irrelevant, selected to 0)
    t0 &= (TT - 1); t1 &= (TT - 1); t2 &= (TT - 1); t3 &= (TT - 1);

    const float* xb = x + ((size_t)b * CC + c0) * TT;

    #pragma unroll
    for (int cb = 0; cb < 32; cb += 4) {
        float4 v[4];
        // batch all 16 gather loads (independent -> MLP ~16)
        #pragma unroll
        for (int j = 0; j < 4; ++j) {
            const float* xr = xb + (size_t)(cb + j) * TT;
            v[j].x = m0 ? __ldg(xr + t0) : 0.0f;
            v[j].y = m1 ? __ldg(xr + t1) : 0.0f;
            v[j].z = m2 ? __ldg(xr + t2) : 0.0f;
            v[j].w = m3 ? __ldg(xr + t3) : 0.0f;
        }
        // then the 4 wide streaming stores
        #pragma unroll
        for (int j = 0; j < 4; ++j)
            __stcs(reinterpret_cast<float4*>(ob + (size_t)(cb + j) * MF), v[j]);
    }
}

extern "C" void kernel_launch(void* const* d_in, const int* in_sizes, int n_in,
                              void* d_out, int out_size) {
    const float* x         = (const float*)d_in[0];
    const float* notepitch = (const float*)d_in[1];
    const float* duration  = (const float*)d_in[2];
    // d_in[3] = x_lengths: unused by the reference computation
    float* out = (float*)d_out;

    prep_kernel<<<BB, TT>>>(duration, notepitch, out);
    expand_kernel<<<dim3(MF / 512, CC / 32, BB), 128>>>(x, out);
}

// round 9
// speedup vs baseline: 1.2502x; 1.1804x over previous
#include <cuda_runtime.h>
#include <cstdint>

#define BB 32
#define CC 384
#define TT 512
#define MF 6656  // MAX_FRAMES = 512*13

// Scratch token map: tok[b][p] = source token index, -1 = masked
__device__ int16_t g_tok[BB * MF];

// ---------------------------------------------------------------------------
// prep: grid (13, BB) x 512 threads. Each block redundantly computes the
// per-batch scan, then does a coalesced searchsorted fill of tok + pitch
// for its 512 frames. frame_lengths written by blockIdx.x==0.
// ---------------------------------------------------------------------------
__global__ void prep_kernel(const float* __restrict__ duration,
                            const float* __restrict__ notepitch,
                            float* __restrict__ out) {
    const int b = blockIdx.y;
    const int t = threadIdx.x;  // 0..511
    __shared__ int   s[TT];     // inclusive cumsum
    __shared__ float sp[TT];    // pitch values (int-cast)

    // repeat count, bit-exact vs jax float32 reference
    const float d  = duration[b * TT + t];
    const float fr = 44100.0f * d;
    float rf;
    if (fr - 1024.0f > 0.0f)
        rf = fmaxf((fr - 1024.0f) * (1.0f / 256.0f), 1.0f);  // /256 exact
    else
        rf = (d == 0.0f) ? 0.0f : 1.0f;
    const int r = (int)rf;

    sp[t] = (float)(int)notepitch[b * TT + t];

    // inclusive block scan (Hillis-Steele)
    s[t] = r;
    __syncthreads();
    #pragma unroll
    for (int off = 1; off < TT; off <<= 1) {
        int v = (t >= off) ? s[t - off] : 0;
        __syncthreads();
        s[t] += v;
        __syncthreads();
    }
    const int flen = s[TT - 1];

    float*   pitch_out = out + (size_t)BB * CC * MF + (size_t)b * MF;
    int16_t* tokb      = g_tok + b * MF;

    // this block's frame
    const int p = blockIdx.x * TT + t;
    if (p < flen) {
        // searchsorted(right): idx = #elements of cum <= p
        int idx = 0;
        #pragma unroll
        for (int step = 256; step > 0; step >>= 1) {
            int cand = idx + step;
            if (cand <= TT && s[cand - 1] <= p) idx = cand;
        }
        tokb[p]      = (int16_t)idx;   // p < flen guarantees idx <= 511
        pitch_out[p] = sp[idx];
    } else {
        tokb[p]      = -1;
        pitch_out[p] = 0.0f;
    }
    if (blockIdx.x == 0 && t == 0) {
        out[(size_t)BB * CC * MF + (size_t)BB * MF + b] = (float)flen;
    }
}

// ---------------------------------------------------------------------------
// expand: out[b, c, p] = tok[p]>=0 ? x[b, c, tok[p]] : 0
// grid = (MF/512, CC/32, BB), block = 128 threads, 4 frames/thread.
// Warp-uniform paths (no syncs, no smem):
//   (a) fully-masked warp  -> pure zero stores
//   (b) token span <= 32   -> 1 coalesced 128B window load + shuffle gather
//       (shuffles executed UNCONDITIONALLY by all lanes -- no divergent shfl)
//   (c) fallback           -> direct gmem gather
// ---------------------------------------------------------------------------
__global__ void __launch_bounds__(128) expand_kernel(
        const float* __restrict__ x,
        float* __restrict__ out) {
    const int b    = blockIdx.z;
    const int c0   = blockIdx.y * 32;
    const int tid  = threadIdx.x;
    const int lane = tid & 31;
    const int p0   = blockIdx.x * 512 + tid * 4;

    const short4 tk4 = *reinterpret_cast<const short4*>(g_tok + b * MF + p0);
    int t0 = tk4.x, t1 = tk4.y, t2 = tk4.z, t3 = tk4.w;
    const bool m0 = t0 >= 0, m1 = t1 >= 0, m2 = t2 >= 0, m3 = t3 >= 0;

    float* ob = out + ((size_t)b * CC + c0) * MF + p0;

    // warp min/max over valid tokens (all lanes participate)
    int mn = 0x7fffffff, mx = -1;
    if (m0) { mn = min(mn, t0); mx = max(mx, t0); }
    if (m1) { mn = min(mn, t1); mx = max(mx, t1); }
    if (m2) { mn = min(mn, t2); mx = max(mx, t2); }
    if (m3) { mn = min(mn, t3); mx = max(mx, t3); }
    #pragma unroll
    for (int o = 16; o > 0; o >>= 1) {
        mn = min(mn, __shfl_xor_sync(0xffffffffu, mn, o));
        mx = max(mx, __shfl_xor_sync(0xffffffffu, mx, o));
    }

    if (mx < 0) {
        // fully-masked warp: pure zero stores
        const float4 z = make_float4(0.f, 0.f, 0.f, 0.f);
        #pragma unroll 8
        for (int c = 0; c < 32; ++c)
            *reinterpret_cast<float4*>(ob + (size_t)c * MF) = z;
        return;
    }

    const float* xb   = x + ((size_t)b * CC + c0) * TT;
    const int    span = mx - mn + 1;  // >= 1, warp-uniform

    if (span <= 32) {
        // shuffle gather: one coalesced window load per channel.
        // Masked lanes use source index 0 (always valid); selection happens
        // AFTER the shuffle so every shfl executes convergently.
        const int i0 = m0 ? (t0 - mn) : 0;
        const int i1 = m1 ? (t1 - mn) : 0;
        const int i2 = m2 ? (t2 - mn) : 0;
        const int i3 = m3 ? (t3 - mn) : 0;
        const bool inw = lane < span;

        #pragma unroll 4
        for (int c = 0; c < 32; ++c) {
            const float* xr = xb + (size_t)c * TT;
            const float  w  = inw ? xr[mn + lane] : 0.0f;  // 128B coalesced
            const float s0 = __shfl_sync(0xffffffffu, w, i0);
            const float s1 = __shfl_sync(0xffffffffu, w, i1);
            const float s2 = __shfl_sync(0xffffffffu, w, i2);
            const float s3 = __shfl_sync(0xffffffffu, w, i3);
            float4 v;
            v.x = m0 ? s0 : 0.0f;
            v.y = m1 ? s1 : 0.0f;
            v.z = m2 ? s2 : 0.0f;
            v.w = m3 ? s3 : 0.0f;
            *reinterpret_cast<float4*>(ob + (size_t)c * MF) = v;
        }
    } else {
        // fallback: direct gmem gather (R1-identical, known correct)
        const int a0 = t0 & (TT - 1), a1 = t1 & (TT - 1);
        const int a2 = t2 & (TT - 1), a3 = t3 & (TT - 1);
        #pragma unroll 4
        for (int c = 0; c < 32; ++c) {
            const float* xr = xb + (size_t)c * TT;
            float4 v;
            v.x = m0 ? xr[a0] : 0.0f;
            v.y = m1 ? xr[a1] : 0.0f;
            v.z = m2 ? xr[a2] : 0.0f;
            v.w = m3 ? xr[a3] : 0.0f;
            *reinterpret_cast<float4*>(ob + (size_t)c * MF) = v;
        }
    }
}

extern "C" void kernel_launch(void* const* d_in, const int* in_sizes, int n_in,
                              void* d_out, int out_size) {
    const float* x         = (const float*)d_in[0];
    const float* notepitch = (const float*)d_in[1];
    const float* duration  = (const float*)d_in[2];
    // d_in[3] = x_lengths: unused by the reference computation
    float* out = (float*)d_out;

    prep_kernel<<<dim3(MF / TT, BB), TT>>>(duration, notepitch, out);
    expand_kernel<<<dim3(MF / 512, CC / 32, BB), 128>>>(x, out);
}

// round 11
// speedup vs baseline: 1.3025x; 1.0418x over previous
#include <cuda_runtime.h>
#include <cstdint>

#define BB 32
#define CC 384
#define TT 512
#define MF 6656  // MAX_FRAMES = 512*13

// ---------------------------------------------------------------------------
// Fused kernel: grid (13, 12, 32), block 128.
//   Phase 1 (inline prep): 128-thread scan over this batch's 512 repeat
//     counts -> inclusive cumsum in smem (int-exact, bit-exact float front).
//   Phase 2: per-frame token via binary search in smem; then the R9 expand
//     paths (zero-store / shuffle-gather / direct-gather).
//   blockIdx.y==0 additionally writes pitch; (y==0,x==0,tid==0) writes flen.
// ---------------------------------------------------------------------------
__global__ void __launch_bounds__(128) fused_kernel(
        const float* __restrict__ x,
        const float* __restrict__ notepitch,
        const float* __restrict__ duration,
        float* __restrict__ out) {
    const int b    = blockIdx.z;
    const int c0   = blockIdx.y * 32;
    const int tid  = threadIdx.x;        // 0..127
    const int lane = tid & 31;
    const int wid  = tid >> 5;           // 0..3
    const int p0   = blockIdx.x * 512 + tid * 4;

    __shared__ int   s[TT];      // inclusive cumsum of repeat counts
    __shared__ float sp[TT];     // pitch values (only used by y==0 blocks)
    __shared__ int   wsum[4];

    // ---- Phase 1: repeat counts + scan (each thread owns 4 tokens) ----
    const float4 d4 = *reinterpret_cast<const float4*>(duration + b * TT + 4 * tid);
    int r[4];
    {
        const float dv[4] = {d4.x, d4.y, d4.z, d4.w};
        #pragma unroll
        for (int j = 0; j < 4; ++j) {
            const float fr = 44100.0f * dv[j];
            float rf;
            if (fr - 1024.0f > 0.0f)
                rf = fmaxf((fr - 1024.0f) * (1.0f / 256.0f), 1.0f);  // /256 exact
            else
                rf = (dv[j] == 0.0f) ? 0.0f : 1.0f;
            r[j] = (int)rf;
        }
    }
    const int tsum = r[0] + r[1] + r[2] + r[3];
    int incl = tsum;
    #pragma unroll
    for (int o = 1; o < 32; o <<= 1) {
        const int v = __shfl_up_sync(0xffffffffu, incl, o);
        if (lane >= o) incl += v;
    }
    if (lane == 31) wsum[wid] = incl;

    if (blockIdx.y == 0) {
        const float4 np = *reinterpret_cast<const float4*>(notepitch + b * TT + 4 * tid);
        sp[4 * tid + 0] = (float)(int)np.x;
        sp[4 * tid + 1] = (float)(int)np.y;
        sp[4 * tid + 2] = (float)(int)np.z;
        sp[4 * tid + 3] = (float)(int)np.w;
    }
    __syncthreads();
    int woff = 0;
    #pragma unroll
    for (int i = 0; i < 4; ++i) woff += (i < wid) ? wsum[i] : 0;
    const int excl = woff + (incl - tsum);
    const int s0 = excl + r[0];
    const int s1 = s0 + r[1];
    const int s2 = s1 + r[2];
    const int s3 = s2 + r[3];
    s[4 * tid + 0] = s0;
    s[4 * tid + 1] = s1;
    s[4 * tid + 2] = s2;
    s[4 * tid + 3] = s3;
    __syncthreads();
    const int flen = s[TT - 1];

    // ---- Phase 2: tokens for this thread's 4 frames ----
    int tk[4];
    bool msk[4];
    #pragma unroll
    for (int j = 0; j < 4; ++j) {
        const int p = p0 + j;
        msk[j] = p < flen;
        int idx = 0;
        if (msk[j]) {
            // searchsorted(right): idx = #elements of cum <= p  (<= 511 since p < flen)
            #pragma unroll
            for (int step = 256; step > 0; step >>= 1) {
                const int cand = idx + step;
                if (cand <= TT && s[cand - 1] <= p) idx = cand;
            }
        }
        tk[j] = idx;
    }
    const bool m0 = msk[0], m1 = msk[1], m2 = msk[2], m3 = msk[3];
    const int  t0 = tk[0],  t1 = tk[1],  t2 = tk[2],  t3 = tk[3];

    // pitch + flen outputs (y==0 slice only)
    if (blockIdx.y == 0) {
        float* pitch_out = out + (size_t)BB * CC * MF + (size_t)b * MF;
        float4 pv;
        pv.x = m0 ? sp[t0] : 0.0f;
        pv.y = m1 ? sp[t1] : 0.0f;
        pv.z = m2 ? sp[t2] : 0.0f;
        pv.w = m3 ? sp[t3] : 0.0f;
        *reinterpret_cast<float4*>(pitch_out + p0) = pv;
        if (blockIdx.x == 0 && tid == 0)
            out[(size_t)BB * CC * MF + (size_t)BB * MF + b] = (float)flen;
    }

    float* ob = out + ((size_t)b * CC + c0) * MF + p0;

    // warp min/max over valid tokens
    int mn = 0x7fffffff, mx = -1;
    if (m0) { mn = min(mn, t0); mx = max(mx, t0); }
    if (m1) { mn = min(mn, t1); mx = max(mx, t1); }
    if (m2) { mn = min(mn, t2); mx = max(mx, t2); }
    if (m3) { mn = min(mn, t3); mx = max(mx, t3); }
    #pragma unroll
    for (int o = 16; o > 0; o >>= 1) {
        mn = min(mn, __shfl_xor_sync(0xffffffffu, mn, o));
        mx = max(mx, __shfl_xor_sync(0xffffffffu, mx, o));
    }

    if (mx < 0) {
        // fully-masked warp: pure zero stores
        const float4 z = make_float4(0.f, 0.f, 0.f, 0.f);
        #pragma unroll 8
        for (int c = 0; c < 32; ++c)
            *reinterpret_cast<float4*>(ob + (size_t)c * MF) = z;
        return;
    }

    const float* xb   = x + ((size_t)b * CC + c0) * TT;
    const int    span = mx - mn + 1;  // >= 1, warp-uniform

    if (span <= 32) {
        // shuffle gather: one coalesced 128B window load per channel.
        // All shuffles execute convergently; selection after.
        const int i0 = m0 ? (t0 - mn) : 0;
        const int i1 = m1 ? (t1 - mn) : 0;
        const int i2 = m2 ? (t2 - mn) : 0;
        const int i3 = m3 ? (t3 - mn) : 0;
        const bool inw = lane < span;

        #pragma unroll 4
        for (int c = 0; c < 32; ++c) {
            const float* xr = xb + (size_t)c * TT;
            const float  w  = inw ? xr[mn + lane] : 0.0f;
            const float sh0 = __shfl_sync(0xffffffffu, w, i0);
            const float sh1 = __shfl_sync(0xffffffffu, w, i1);
            const float sh2 = __shfl_sync(0xffffffffu, w, i2);
            const float sh3 = __shfl_sync(0xffffffffu, w, i3);
            float4 v;
            v.x = m0 ? sh0 : 0.0f;
            v.y = m1 ? sh1 : 0.0f;
            v.z = m2 ? sh2 : 0.0f;
            v.w = m3 ? sh3 : 0.0f;
            *reinterpret_cast<float4*>(ob + (size_t)c * MF) = v;
        }
    } else {
        // fallback: direct gmem gather
        const int a0 = t0 & (TT - 1), a1 = t1 & (TT - 1);
        const int a2 = t2 & (TT - 1), a3 = t3 & (TT - 1);
        #pragma unroll 4
        for (int c = 0; c < 32; ++c) {
            const float* xr = xb + (size_t)c * TT;
            float4 v;
            v.x = m0 ? xr[a0] : 0.0f;
            v.y = m1 ? xr[a1] : 0.0f;
            v.z = m2 ? xr[a2] : 0.0f;
            v.w = m3 ? xr[a3] : 0.0f;
            *reinterpret_cast<float4*>(ob + (size_t)c * MF) = v;
        }
    }
}

extern "C" void kernel_launch(void* const* d_in, const int* in_sizes, int n_in,
                              void* d_out, int out_size) {
    const float* x         = (const float*)d_in[0];
    const float* notepitch = (const float*)d_in[1];
    const float* duration  = (const float*)d_in[2];
    // d_in[3] = x_lengths: unused by the reference computation
    float* out = (float*)d_out;

    fused_kernel<<<dim3(MF / 512, CC / 32, BB), 128>>>(x, notepitch, duration, out);
}